// round 15
// baseline (speedup 1.0000x reference)
#include <cuda_runtime.h>
#include <cuda_fp16.h>
#include <math.h>
#include <stdint.h>

#define B_   16
#define C_   512
#define NSP  1024
#define NG   32
#define GC   16
#define NH   8
#define HD   64

__device__ __half g_h   [(size_t)B_ * C_ * NSP];
__device__ __half g_qkv [(size_t)B_ * 3 * C_ * NSP];
__device__ __half g_ao  [(size_t)B_ * C_ * NSP];
__device__ __half g_wqkv[(size_t)3 * C_ * C_];
__device__ __half g_wprj[(size_t)C_ * C_];

__device__ __forceinline__ float ex2(float x) {
    float y; asm("ex2.approx.ftz.f32 %0, %1;" : "=f"(y) : "f"(x)); return y;
}
__device__ __forceinline__ uint32_t h2ex2(uint32_t x) {
    uint32_t y; asm("ex2.approx.f16x2 %0, %1;" : "=r"(y) : "r"(x)); return y;
}
__device__ __forceinline__ void gdc_wait() {
    asm volatile("griddepcontrol.wait;" ::: "memory");
}
__device__ __forceinline__ void mmaf16(float (&d)[4], const uint32_t* a, uint32_t b0, uint32_t b1) {
    asm volatile("mma.sync.aligned.m16n8k16.row.col.f32.f16.f16.f32 "
                 "{%0,%1,%2,%3}, {%4,%5,%6,%7}, {%8,%9}, {%0,%1,%2,%3};\n"
                 : "+f"(d[0]), "+f"(d[1]), "+f"(d[2]), "+f"(d[3])
                 : "r"(a[0]), "r"(a[1]), "r"(a[2]), "r"(a[3]), "r"(b0), "r"(b1));
}
__device__ __forceinline__ void ldsm4(uint32_t& r0, uint32_t& r1, uint32_t& r2, uint32_t& r3, uint32_t a) {
    asm volatile("ldmatrix.sync.aligned.m8n8.x4.shared.b16 {%0,%1,%2,%3}, [%4];\n"
                 : "=r"(r0), "=r"(r1), "=r"(r2), "=r"(r3) : "r"(a));
}
__device__ __forceinline__ void ldsm4t(uint32_t& r0, uint32_t& r1, uint32_t& r2, uint32_t& r3, uint32_t a) {
    asm volatile("ldmatrix.sync.aligned.m8n8.x4.trans.shared.b16 {%0,%1,%2,%3}, [%4];\n"
                 : "=r"(r0), "=r"(r1), "=r"(r2), "=r"(r3) : "r"(a));
}
__device__ __forceinline__ uint32_t packh2(float lo, float hi) {
    __half2 h = __floats2half2_rn(lo, hi);
    return *reinterpret_cast<uint32_t*>(&h);
}
__device__ __forceinline__ void cpa16(uint32_t dst, const void* src) {
    asm volatile("cp.async.cg.shared.global [%0], [%1], 16;" :: "r"(dst), "l"(src));
}
#define CP_COMMIT asm volatile("cp.async.commit_group;")
#define CP_WAIT0  asm volatile("cp.async.wait_group 0;")

// ---------------------------------------------------------------------------
// Fused prologue: GroupNorm (blocks 0..511) + weight conversions (512..1023)
// ---------------------------------------------------------------------------
__global__ __launch_bounds__(512) void prolog_kernel(const float* __restrict__ x,
                                                     const float* __restrict__ gamma,
                                                     const float* __restrict__ beta,
                                                     __half* __restrict__ hout,
                                                     const float* __restrict__ wq,
                                                     __half* __restrict__ wqh,
                                                     const float* __restrict__ wp,
                                                     __half* __restrict__ wph) {
    int bx = blockIdx.x;
    int tid = threadIdx.x;

    if (bx >= 512) {
        if (bx < 896) {
            int i = (bx - 512) * 512 + tid;
            float4 v = ((const float4*)wq)[i];
            uint2 o;
            o.x = packh2(v.x, v.y);
            o.y = packh2(v.z, v.w);
            ((uint2*)wqh)[i] = o;
        } else {
            int i = (bx - 896) * 512 + tid;
            float4 v = ((const float4*)wp)[i];
            uint2 o;
            o.x = packh2(v.x, v.y);
            o.y = packh2(v.z, v.w);
            ((uint2*)wph)[i] = o;
        }
        return;
    }

    int b = bx >> 5;
    int g = bx & 31;
    const float4* xp = (const float4*)(x + ((size_t)b * C_ + g * GC) * NSP);
    uint2* hp = (uint2*)(hout + ((size_t)b * C_ + g * GC) * NSP);

    float s = 0.f, ss = 0.f;
    float4 v[8];
    #pragma unroll
    for (int i = 0; i < 8; i++) {
        v[i] = xp[tid + i * 512];
        s  += v[i].x + v[i].y + v[i].z + v[i].w;
        ss += v[i].x * v[i].x + v[i].y * v[i].y + v[i].z * v[i].z + v[i].w * v[i].w;
    }
    __shared__ float rs[512], rss[512];
    rs[tid] = s; rss[tid] = ss;
    __syncthreads();
    for (int off = 256; off > 0; off >>= 1) {
        if (tid < off) { rs[tid] += rs[tid + off]; rss[tid] += rss[tid + off]; }
        __syncthreads();
    }
    const float invn = 1.f / (GC * NSP);
    float mean = rs[0] * invn;
    float var  = rss[0] * invn - mean * mean;
    float inv  = rsqrtf(var + 1e-5f);

    #pragma unroll
    for (int i = 0; i < 8; i++) {
        int idx = tid + i * 512;
        int cl = idx >> 8;
        float ga = gamma[g * GC + cl] * inv;
        float be = beta [g * GC + cl];
        uint2 o;
        o.x = packh2((v[i].x - mean) * ga + be, (v[i].y - mean) * ga + be);
        o.y = packh2((v[i].z - mean) * ga + be, (v[i].w - mean) * ga + be);
        hp[idx] = o;
    }
}

// ---------------------------------------------------------------------------
// fp16 GEMM (both stages): 128x128 block tile, 128 threads, warp tile 64x64.
// k-chunk 64, 2-stage, 1 barrier/chunk. PDL wait before first load.
// ---------------------------------------------------------------------------
#define GSTG   35840
#define GSMEM  (2 * GSTG)

__global__ __launch_bounds__(128, 2) void gemm_f16(const __half* __restrict__ W,
                                                   const __half* __restrict__ Hin,
                                                   const float* __restrict__ bias,
                                                   const float* __restrict__ X,
                                                   float* __restrict__ Out,
                                                   __half* __restrict__ OutH) {
    extern __shared__ char gsm[];
    const int M = gridDim.y * 128;
    const __half* Hb = Hin + (size_t)blockIdx.z * C_ * NSP;
    int m0 = blockIdx.y * 128, n0 = blockIdx.x * 128;
    int tid = threadIdx.x;
    int w = tid >> 5, l = tid & 31;
    int r = l >> 2, c = l & 3;
    int wm = (w & 1) * 64, wn = (w >> 1) * 64;

    uint32_t smb = (uint32_t)__cvta_generic_to_shared(gsm);

    auto issue = [&](int ch) {
        int c0 = ch * 64;
        uint32_t base = smb + (uint32_t)((ch & 1) * GSTG);
        #pragma unroll
        for (int t = 0; t < 8; t++) {
            int idx = tid + t * 128;
            int row = idx >> 3, col8 = (idx & 7) * 8;
            cpa16(base + (row * 72 + col8) * 2, &W[(size_t)(m0 + row) * C_ + c0 + col8]);
        }
        #pragma unroll
        for (int t = 0; t < 8; t++) {
            int idx = tid + t * 128;
            int row = idx >> 4, col8 = (idx & 15) * 8;
            cpa16(base + 18432 + (row * 136 + col8) * 2,
                  &Hb[(size_t)(c0 + row) * NSP + n0 + col8]);
        }
        CP_COMMIT;
    };

    uint32_t aoff = ((wm + (l & 15)) * 72 + (l >> 4) * 8) * 2;
    uint32_t boff = (((l & 7) + ((l >> 3) & 1) * 8) * 136 + wn + (l >> 4) * 8) * 2;

    float acc[4][8][4];
    #pragma unroll
    for (int i = 0; i < 4; i++)
        #pragma unroll
        for (int j = 0; j < 8; j++)
            #pragma unroll
            for (int k = 0; k < 4; k++) acc[i][j][k] = 0.f;

    gdc_wait();
    issue(0);

    for (int ch = 0; ch < 8; ch++) {
        CP_WAIT0;
        __syncthreads();
        if (ch < 7) issue(ch + 1);
        uint32_t ab = smb + (uint32_t)((ch & 1) * GSTG);
        uint32_t bb = ab + 18432;

        #pragma unroll
        for (int ks = 0; ks < 4; ks++) {
            uint32_t a[4][4];
            #pragma unroll
            for (int i = 0; i < 4; i++)
                ldsm4(a[i][0], a[i][1], a[i][2], a[i][3],
                      ab + aoff + (uint32_t)(i * 2304) + ks * 32);
            #pragma unroll
            for (int j = 0; j < 4; j++) {
                uint32_t bq[4];
                ldsm4t(bq[0], bq[1], bq[2], bq[3], bb + boff + ks * 4352 + j * 32);
                #pragma unroll
                for (int i = 0; i < 4; i++) {
                    mmaf16(acc[i][2 * j],     a[i], bq[0], bq[1]);
                    mmaf16(acc[i][2 * j + 1], a[i], bq[2], bq[3]);
                }
            }
        }
    }

    #pragma unroll
    for (int i = 0; i < 4; i++) {
        int mrow = m0 + wm + i * 16 + r;
        float bv0 = bias[mrow], bv1 = bias[mrow + 8];
        #pragma unroll
        for (int j = 0; j < 8; j++) {
            int col = n0 + wn + j * 8 + 2 * c;
            size_t i0 = (size_t)mrow * NSP + col;
            size_t i1 = (size_t)(mrow + 8) * NSP + col;
            float2 v0 = {acc[i][j][0] + bv0, acc[i][j][1] + bv0};
            float2 v1 = {acc[i][j][2] + bv1, acc[i][j][3] + bv1};
            if (OutH) {
                __half* OHb = OutH + (size_t)blockIdx.z * M * NSP;
                *(uint32_t*)&OHb[i0] = packh2(v0.x, v0.y);
                *(uint32_t*)&OHb[i1] = packh2(v1.x, v1.y);
            } else {
                const float* Xb = X + (size_t)blockIdx.z * M * NSP;
                float*       Ob = Out + (size_t)blockIdx.z * M * NSP;
                float2 x0 = *(const float2*)&Xb[i0];
                float2 x1 = *(const float2*)&Xb[i1];
                v0.x += x0.x; v0.y += x0.y;
                v1.x += x1.x; v1.y += x1.y;
                *(float2*)&Ob[i0] = v0;
                *(float2*)&Ob[i1] = v1;
            }
        }
    }
}

// ---------------------------------------------------------------------------
// fp16 flash attention. 64 q / 128 thr / 4 CTAs/SM. Single barrier per tile.
// Row sums on the scalar pipe (fp32, from the fp16 P fragments) — no ones-MMA.
// ---------------------------------------------------------------------------
#define ATTN_SMEM 46080

__global__ __launch_bounds__(128, 4) void attn_f16(const __half* __restrict__ qkv,
                                                   __half* __restrict__ ao) {
    extern __shared__ char smc[];
    __half* Qs = (__half*)smc;

    int qt = blockIdx.x, hh = blockIdx.y, b = blockIdx.z;
    const __half* qb = qkv + ((size_t)b * (3 * C_) + hh * HD) * NSP;
    const __half* kb = qb + (size_t)C_ * NSP;
    const __half* vb = qb + (size_t)2 * C_ * NSP;
    int n0 = qt * 64;
    int tid = threadIdx.x, w = tid >> 5, l = tid & 31;
    int r = l >> 2, c = l & 3;
    int prow = w * 16;

    uint32_t smb = (uint32_t)__cvta_generic_to_shared(smc);
    uint32_t kbuf[2] = {smb + 9216, smb + 27648};
    uint32_t qa   = smb + (((l & 7) + (l >> 4) * 8) * 72 + prow + ((l >> 3) & 1) * 8) * 2;
    uint32_t koff = (((l & 7) + ((l >> 3) & 1) * 8) * 72 + (l >> 4) * 8) * 2;
    uint32_t voff = 9216 + (((l & 7) + (l >> 4) * 8) * 72 + ((l >> 3) & 1) * 8) * 2;

    int cr = tid >> 3, cc = (tid & 7) * 8;
    auto issue = [&](int kt, int s) {
        int mk0 = kt * 64;
        uint32_t kd = kbuf[s];
        #pragma unroll
        for (int i = 0; i < 4; i++) {
            int row = cr + i * 16;
            cpa16(kd + (row * 72 + cc) * 2,        &kb[(size_t)row * NSP + mk0 + cc]);
            cpa16(kd + 9216 + (row * 72 + cc) * 2, &vb[(size_t)row * NSP + mk0 + cc]);
        }
        CP_COMMIT;
    };

    gdc_wait();

    #pragma unroll
    for (int i = 0; i < 8; i++) {
        int f = tid + i * 128;
        int d = f >> 4, n4 = (f & 15) * 4;
        *(uint2*)&Qs[d * 72 + n4] = *(const uint2*)&qb[(size_t)d * NSP + n0 + n4];
    }

    float o[8][4];
    #pragma unroll
    for (int j = 0; j < 8; j++)
        #pragma unroll
        for (int k = 0; k < 4; k++) o[j][k] = 0.f;
    float l0 = 0.f, l1 = 0.f;
    float mr0 = -1e30f, mr1 = -1e30f;
    const float csc = 0.125f * 1.4426950408889634f;

    issue(0, 0);

    for (int kt = 0; kt < 16; kt++) {
        int s = kt & 1;
        CP_WAIT0;
        __syncthreads();
        if (kt < 15) issue(kt + 1, s ^ 1);
        uint32_t ka = kbuf[s] + koff;
        uint32_t va = kbuf[s] + voff;

        float sc[8][4];
        #pragma unroll
        for (int j = 0; j < 8; j++)
            #pragma unroll
            for (int k = 0; k < 4; k++) sc[j][k] = 0.f;
        #pragma unroll
        for (int dk = 0; dk < 4; dk++) {
            uint32_t a[4];
            ldsm4t(a[0], a[1], a[2], a[3], qa + dk * 16 * 144);
            #pragma unroll
            for (int jj = 0; jj < 4; jj++) {
                uint32_t bq[4];
                ldsm4t(bq[0], bq[1], bq[2], bq[3], ka + dk * 16 * 144 + jj * 32);
                mmaf16(sc[2 * jj], a, bq[0], bq[1]);
                mmaf16(sc[2 * jj + 1], a, bq[2], bq[3]);
            }
        }

        float tm0 = -1e30f, tm1 = -1e30f;
        #pragma unroll
        for (int j = 0; j < 8; j++) {
            tm0 = fmaxf(tm0, fmaxf(sc[j][0], sc[j][1]));
            tm1 = fmaxf(tm1, fmaxf(sc[j][2], sc[j][3]));
        }
        tm0 = fmaxf(tm0, __shfl_xor_sync(0xffffffffu, tm0, 1));
        tm0 = fmaxf(tm0, __shfl_xor_sync(0xffffffffu, tm0, 2));
        tm1 = fmaxf(tm1, __shfl_xor_sync(0xffffffffu, tm1, 1));
        tm1 = fmaxf(tm1, __shfl_xor_sync(0xffffffffu, tm1, 2));
        float nm0 = fmaxf(mr0, tm0), nm1 = fmaxf(mr1, tm1);
        float cr0f = ex2((mr0 - nm0) * csc), cr1f = ex2((mr1 - nm1) * csc);
        mr0 = nm0; mr1 = nm1;
        float b0 = nm0 * csc, b1 = nm1 * csc;

        // P = exp2(s*csc - b), fp16x2 fragments (A operand for PV)
        uint32_t ph[16];
        #pragma unroll
        for (int q = 0; q < 8; q++) {
            ph[2 * q]     = h2ex2(packh2(fmaf(sc[q][0], csc, -b0), fmaf(sc[q][1], csc, -b0)));
            ph[2 * q + 1] = h2ex2(packh2(fmaf(sc[q][2], csc, -b1), fmaf(sc[q][3], csc, -b1)));
        }

        // Row sums on scalar pipe from the SAME fp16 P the MMA will consume
        float sum0 = 0.f, sum1 = 0.f;
        #pragma unroll
        for (int q = 0; q < 8; q++) {
            float2 f0 = __half22float2(*(const __half2*)&ph[2 * q]);
            float2 f1 = __half22float2(*(const __half2*)&ph[2 * q + 1]);
            sum0 += f0.x + f0.y;
            sum1 += f1.x + f1.y;
        }
        sum0 += __shfl_xor_sync(0xffffffffu, sum0, 1);
        sum0 += __shfl_xor_sync(0xffffffffu, sum0, 2);
        sum1 += __shfl_xor_sync(0xffffffffu, sum1, 1);
        sum1 += __shfl_xor_sync(0xffffffffu, sum1, 2);
        l0 = l0 * cr0f + sum0;
        l1 = l1 * cr1f + sum1;

        #pragma unroll
        for (int j = 0; j < 8; j++) {
            o[j][0] *= cr0f; o[j][1] *= cr0f;
            o[j][2] *= cr1f; o[j][3] *= cr1f;
        }

        // O += P @ V^T  (no ones-MMA)
        #pragma unroll
        for (int kk = 0; kk < 4; kk++) {
            #pragma unroll
            for (int dd = 0; dd < 4; dd++) {
                uint32_t bv[4];
                ldsm4(bv[0], bv[1], bv[2], bv[3], va + dd * 16 * 144 + kk * 32);
                mmaf16(o[2 * dd],     &ph[4 * kk], bv[0], bv[1]);
                mmaf16(o[2 * dd + 1], &ph[4 * kk], bv[2], bv[3]);
            }
        }
    }

    float il0 = 1.f / l0, il1 = 1.f / l1;
    __syncthreads();
    __half* Osm = (__half*)smc;   // [64 d][72 q]
    #pragma unroll
    for (int j = 0; j < 8; j++) {
        int d = 8 * j + 2 * c;
        Osm[(d)     * 72 + prow + r]     = __float2half(o[j][0] * il0);
        Osm[(d + 1) * 72 + prow + r]     = __float2half(o[j][1] * il0);
        Osm[(d)     * 72 + prow + r + 8] = __float2half(o[j][2] * il1);
        Osm[(d + 1) * 72 + prow + r + 8] = __float2half(o[j][3] * il1);
    }
    __syncthreads();
    __half* aob = ao + ((size_t)b * C_ + hh * HD) * NSP;
    #pragma unroll
    for (int i = 0; i < 8; i++) {
        int f = tid + i * 128;
        int d = f >> 4, n4 = (f & 15) * 4;
        *(uint2*)&aob[(size_t)d * NSP + n0 + n4] = *(uint2*)&Osm[d * 72 + n4];
    }
}

// ---------------------------------------------------------------------------
extern "C" void kernel_launch(void* const* d_in, const int* in_sizes, int n_in,
                              void* d_out, int out_size) {
    const float* x      = (const float*)d_in[0];
    const float* gamma  = (const float*)d_in[1];
    const float* beta   = (const float*)d_in[2];
    const float* w_qkv  = (const float*)d_in[3];
    const float* b_qkv  = (const float*)d_in[4];
    const float* w_proj = (const float*)d_in[5];
    const float* b_proj = (const float*)d_in[6];
    float* out = (float*)d_out;

    __half *ph, *pq, *pa, *pwq, *pwp;
    cudaGetSymbolAddress((void**)&ph,  g_h);
    cudaGetSymbolAddress((void**)&pq,  g_qkv);
    cudaGetSymbolAddress((void**)&pa,  g_ao);
    cudaGetSymbolAddress((void**)&pwq, g_wqkv);
    cudaGetSymbolAddress((void**)&pwp, g_wprj);

    cudaFuncSetAttribute(attn_f16, cudaFuncAttributeMaxDynamicSharedMemorySize, ATTN_SMEM);
    cudaFuncSetAttribute(gemm_f16, cudaFuncAttributeMaxDynamicSharedMemorySize, GSMEM);

    prolog_kernel<<<1024, 512>>>(x, gamma, beta, ph, w_qkv, pwq, w_proj, pwp);

    cudaLaunchAttribute attrs[1];
    attrs[0].id = cudaLaunchAttributeProgrammaticStreamSerialization;
    attrs[0].val.programmaticStreamSerializationAllowed = 1;

    {   // QKV GEMM
        cudaLaunchConfig_t cfg = {};
        cfg.gridDim = dim3(8, 12, 16);
        cfg.blockDim = dim3(128, 1, 1);
        cfg.dynamicSmemBytes = GSMEM;
        cfg.stream = 0;
        cfg.attrs = attrs;
        cfg.numAttrs = 1;
        cudaLaunchKernelEx(&cfg, gemm_f16, (const __half*)pwq, (const __half*)ph,
                           b_qkv, (const float*)nullptr, (float*)nullptr, pq);
    }
    {   // attention
        cudaLaunchConfig_t cfg = {};
        cfg.gridDim = dim3(16, NH, B_);
        cfg.blockDim = dim3(128, 1, 1);
        cfg.dynamicSmemBytes = ATTN_SMEM;
        cfg.stream = 0;
        cfg.attrs = attrs;
        cfg.numAttrs = 1;
        cudaLaunchKernelEx(&cfg, attn_f16, (const __half*)pq, pa);
    }
    {   // proj GEMM + residual
        cudaLaunchConfig_t cfg = {};
        cfg.gridDim = dim3(8, 4, 16);
        cfg.blockDim = dim3(128, 1, 1);
        cfg.dynamicSmemBytes = GSMEM;
        cfg.stream = 0;
        cfg.attrs = attrs;
        cfg.numAttrs = 1;
        cudaLaunchKernelEx(&cfg, gemm_f16, (const __half*)pwp, (const __half*)pa,
                           b_proj, x, out, (__half*)nullptr);
    }
}

// round 16
// speedup vs baseline: 1.0238x; 1.0238x over previous
#include <cuda_runtime.h>
#include <cuda_fp16.h>
#include <math.h>
#include <stdint.h>

#define B_   16
#define C_   512
#define NSP  1024
#define NG   32
#define GC   16
#define NH   8
#define HD   64

__device__ __half g_h   [(size_t)B_ * C_ * NSP];
__device__ __half g_qkv [(size_t)B_ * 3 * C_ * NSP];
__device__ __half g_ao  [(size_t)B_ * C_ * NSP];
__device__ __half g_wqkv[(size_t)3 * C_ * C_];
__device__ __half g_wprj[(size_t)C_ * C_];

__device__ __forceinline__ float ex2(float x) {
    float y; asm("ex2.approx.ftz.f32 %0, %1;" : "=f"(y) : "f"(x)); return y;
}
__device__ __forceinline__ uint32_t h2ex2(uint32_t x) {
    uint32_t y; asm("ex2.approx.f16x2 %0, %1;" : "=r"(y) : "r"(x)); return y;
}
__device__ __forceinline__ void gdc_wait() {
    asm volatile("griddepcontrol.wait;" ::: "memory");
}
__device__ __forceinline__ void mmaf16(float (&d)[4], const uint32_t* a, uint32_t b0, uint32_t b1) {
    asm volatile("mma.sync.aligned.m16n8k16.row.col.f32.f16.f16.f32 "
                 "{%0,%1,%2,%3}, {%4,%5,%6,%7}, {%8,%9}, {%0,%1,%2,%3};\n"
                 : "+f"(d[0]), "+f"(d[1]), "+f"(d[2]), "+f"(d[3])
                 : "r"(a[0]), "r"(a[1]), "r"(a[2]), "r"(a[3]), "r"(b0), "r"(b1));
}
__device__ __forceinline__ void ldsm4(uint32_t& r0, uint32_t& r1, uint32_t& r2, uint32_t& r3, uint32_t a) {
    asm volatile("ldmatrix.sync.aligned.m8n8.x4.shared.b16 {%0,%1,%2,%3}, [%4];\n"
                 : "=r"(r0), "=r"(r1), "=r"(r2), "=r"(r3) : "r"(a));
}
__device__ __forceinline__ void ldsm4t(uint32_t& r0, uint32_t& r1, uint32_t& r2, uint32_t& r3, uint32_t a) {
    asm volatile("ldmatrix.sync.aligned.m8n8.x4.trans.shared.b16 {%0,%1,%2,%3}, [%4];\n"
                 : "=r"(r0), "=r"(r1), "=r"(r2), "=r"(r3) : "r"(a));
}
__device__ __forceinline__ uint32_t packh2(float lo, float hi) {
    __half2 h = __floats2half2_rn(lo, hi);
    return *reinterpret_cast<uint32_t*>(&h);
}
__device__ __forceinline__ void cpa16(uint32_t dst, const void* src) {
    asm volatile("cp.async.cg.shared.global [%0], [%1], 16;" :: "r"(dst), "l"(src));
}
#define CP_COMMIT asm volatile("cp.async.commit_group;")
#define CP_WAIT0  asm volatile("cp.async.wait_group 0;")

// ---------------------------------------------------------------------------
// Fused prologue: GroupNorm (blocks 0..511) + weight conversions (512..1023)
// ---------------------------------------------------------------------------
__global__ __launch_bounds__(512) void prolog_kernel(const float* __restrict__ x,
                                                     const float* __restrict__ gamma,
                                                     const float* __restrict__ beta,
                                                     __half* __restrict__ hout,
                                                     const float* __restrict__ wq,
                                                     __half* __restrict__ wqh,
                                                     const float* __restrict__ wp,
                                                     __half* __restrict__ wph) {
    int bx = blockIdx.x;
    int tid = threadIdx.x;

    if (bx >= 512) {
        if (bx < 896) {
            int i = (bx - 512) * 512 + tid;
            float4 v = ((const float4*)wq)[i];
            uint2 o;
            o.x = packh2(v.x, v.y);
            o.y = packh2(v.z, v.w);
            ((uint2*)wqh)[i] = o;
        } else {
            int i = (bx - 896) * 512 + tid;
            float4 v = ((const float4*)wp)[i];
            uint2 o;
            o.x = packh2(v.x, v.y);
            o.y = packh2(v.z, v.w);
            ((uint2*)wph)[i] = o;
        }
        return;
    }

    int b = bx >> 5;
    int g = bx & 31;
    const float4* xp = (const float4*)(x + ((size_t)b * C_ + g * GC) * NSP);
    uint2* hp = (uint2*)(hout + ((size_t)b * C_ + g * GC) * NSP);

    float s = 0.f, ss = 0.f;
    float4 v[8];
    #pragma unroll
    for (int i = 0; i < 8; i++) {
        v[i] = xp[tid + i * 512];
        s  += v[i].x + v[i].y + v[i].z + v[i].w;
        ss += v[i].x * v[i].x + v[i].y * v[i].y + v[i].z * v[i].z + v[i].w * v[i].w;
    }
    __shared__ float rs[512], rss[512];
    rs[tid] = s; rss[tid] = ss;
    __syncthreads();
    for (int off = 256; off > 0; off >>= 1) {
        if (tid < off) { rs[tid] += rs[tid + off]; rss[tid] += rss[tid + off]; }
        __syncthreads();
    }
    const float invn = 1.f / (GC * NSP);
    float mean = rs[0] * invn;
    float var  = rss[0] * invn - mean * mean;
    float inv  = rsqrtf(var + 1e-5f);

    #pragma unroll
    for (int i = 0; i < 8; i++) {
        int idx = tid + i * 512;
        int cl = idx >> 8;
        float ga = gamma[g * GC + cl] * inv;
        float be = beta [g * GC + cl];
        uint2 o;
        o.x = packh2((v[i].x - mean) * ga + be, (v[i].y - mean) * ga + be);
        o.y = packh2((v[i].z - mean) * ga + be, (v[i].w - mean) * ga + be);
        hp[idx] = o;
    }
}

// ---------------------------------------------------------------------------
// fp16 GEMM (both stages): 128x128 block tile, 128 threads, warp tile 64x64.
// k-chunk 64, 2-stage, 1 barrier/chunk. PDL wait before first load.
// ---------------------------------------------------------------------------
#define GSTG   35840
#define GSMEM  (2 * GSTG)

__global__ __launch_bounds__(128, 2) void gemm_f16(const __half* __restrict__ W,
                                                   const __half* __restrict__ Hin,
                                                   const float* __restrict__ bias,
                                                   const float* __restrict__ X,
                                                   float* __restrict__ Out,
                                                   __half* __restrict__ OutH) {
    extern __shared__ char gsm[];
    const int M = gridDim.y * 128;
    const __half* Hb = Hin + (size_t)blockIdx.z * C_ * NSP;
    int m0 = blockIdx.y * 128, n0 = blockIdx.x * 128;
    int tid = threadIdx.x;
    int w = tid >> 5, l = tid & 31;
    int r = l >> 2, c = l & 3;
    int wm = (w & 1) * 64, wn = (w >> 1) * 64;

    uint32_t smb = (uint32_t)__cvta_generic_to_shared(gsm);
    uint32_t stga[2] = {smb, smb + GSTG};

    auto issue = [&](int ch) {
        int c0 = ch * 64;
        uint32_t base = stga[ch & 1];
        #pragma unroll
        for (int t = 0; t < 8; t++) {
            int idx = tid + t * 128;
            int row = idx >> 3, col8 = (idx & 7) * 8;
            cpa16(base + (row * 72 + col8) * 2, &W[(size_t)(m0 + row) * C_ + c0 + col8]);
        }
        #pragma unroll
        for (int t = 0; t < 8; t++) {
            int idx = tid + t * 128;
            int row = idx >> 4, col8 = (idx & 15) * 8;
            cpa16(base + 18432 + (row * 136 + col8) * 2,
                  &Hb[(size_t)(c0 + row) * NSP + n0 + col8]);
        }
        CP_COMMIT;
    };

    uint32_t aoff = ((wm + (l & 15)) * 72 + (l >> 4) * 8) * 2;
    uint32_t boff = (((l & 7) + ((l >> 3) & 1) * 8) * 136 + wn + (l >> 4) * 8) * 2;

    gdc_wait();
    issue(0);

    float acc[4][8][4];
    #pragma unroll
    for (int i = 0; i < 4; i++)
        #pragma unroll
        for (int j = 0; j < 8; j++)
            #pragma unroll
            for (int k = 0; k < 4; k++) acc[i][j][k] = 0.f;

    for (int ch = 0; ch < 8; ch++) {
        CP_WAIT0;
        __syncthreads();
        if (ch < 7) issue(ch + 1);
        uint32_t ab = stga[ch & 1];
        uint32_t bb = ab + 18432;

        #pragma unroll
        for (int ks = 0; ks < 4; ks++) {
            uint32_t a[4][4];
            #pragma unroll
            for (int i = 0; i < 4; i++)
                ldsm4(a[i][0], a[i][1], a[i][2], a[i][3],
                      ab + aoff + (uint32_t)(i * 2304) + ks * 32);
            #pragma unroll
            for (int j = 0; j < 4; j++) {
                uint32_t bq[4];
                ldsm4t(bq[0], bq[1], bq[2], bq[3], bb + boff + ks * 4352 + j * 32);
                #pragma unroll
                for (int i = 0; i < 4; i++) {
                    mmaf16(acc[i][2 * j],     a[i], bq[0], bq[1]);
                    mmaf16(acc[i][2 * j + 1], a[i], bq[2], bq[3]);
                }
            }
        }
    }

    #pragma unroll
    for (int i = 0; i < 4; i++) {
        int mrow = m0 + wm + i * 16 + r;
        float bv0 = bias[mrow], bv1 = bias[mrow + 8];
        #pragma unroll
        for (int j = 0; j < 8; j++) {
            int col = n0 + wn + j * 8 + 2 * c;
            size_t i0 = (size_t)mrow * NSP + col;
            size_t i1 = (size_t)(mrow + 8) * NSP + col;
            float2 v0 = {acc[i][j][0] + bv0, acc[i][j][1] + bv0};
            float2 v1 = {acc[i][j][2] + bv1, acc[i][j][3] + bv1};
            if (OutH) {
                __half* OHb = OutH + (size_t)blockIdx.z * M * NSP;
                *(uint32_t*)&OHb[i0] = packh2(v0.x, v0.y);
                *(uint32_t*)&OHb[i1] = packh2(v1.x, v1.y);
            } else {
                const float* Xb = X + (size_t)blockIdx.z * M * NSP;
                float*       Ob = Out + (size_t)blockIdx.z * M * NSP;
                float2 x0 = *(const float2*)&Xb[i0];
                float2 x1 = *(const float2*)&Xb[i1];
                v0.x += x0.x; v0.y += x0.y;
                v1.x += x1.x; v1.y += x1.y;
                *(float2*)&Ob[i0] = v0;
                *(float2*)&Ob[i1] = v1;
            }
        }
    }
}

// ---------------------------------------------------------------------------
// fp16 flash attention. 64 q / 128 thr / 4 CTAs/SM. Ones-MMA row sums (R13).
// First K/V cp.async issued BEFORE the Q LDG loop (entry-latency overlap).
// ---------------------------------------------------------------------------
#define ATTN_SMEM 46080

__global__ __launch_bounds__(128, 4) void attn_f16(const __half* __restrict__ qkv,
                                                   __half* __restrict__ ao) {
    extern __shared__ char smc[];
    __half* Qs = (__half*)smc;

    int qt = blockIdx.x, hh = blockIdx.y, b = blockIdx.z;
    const __half* qb = qkv + ((size_t)b * (3 * C_) + hh * HD) * NSP;
    const __half* kb = qb + (size_t)C_ * NSP;
    const __half* vb = qb + (size_t)2 * C_ * NSP;
    int n0 = qt * 64;
    int tid = threadIdx.x, w = tid >> 5, l = tid & 31;
    int r = l >> 2, c = l & 3;
    int prow = w * 16;

    uint32_t smb = (uint32_t)__cvta_generic_to_shared(smc);
    uint32_t kbuf[2] = {smb + 9216, smb + 27648};
    uint32_t qa   = smb + (((l & 7) + (l >> 4) * 8) * 72 + prow + ((l >> 3) & 1) * 8) * 2;
    uint32_t koff = (((l & 7) + ((l >> 3) & 1) * 8) * 72 + (l >> 4) * 8) * 2;
    uint32_t voff = 9216 + (((l & 7) + (l >> 4) * 8) * 72 + ((l >> 3) & 1) * 8) * 2;

    int cr = tid >> 3, cc = (tid & 7) * 8;
    auto issue = [&](int kt, int s) {
        int mk0 = kt * 64;
        uint32_t kd = kbuf[s];
        #pragma unroll
        for (int i = 0; i < 4; i++) {
            int row = cr + i * 16;
            cpa16(kd + (row * 72 + cc) * 2,        &kb[(size_t)row * NSP + mk0 + cc]);
            cpa16(kd + 9216 + (row * 72 + cc) * 2, &vb[(size_t)row * NSP + mk0 + cc]);
        }
        CP_COMMIT;
    };

    gdc_wait();
    issue(0, 0);     // K/V tile 0 in flight before Q loads

    #pragma unroll
    for (int i = 0; i < 8; i++) {
        int f = tid + i * 128;
        int d = f >> 4, n4 = (f & 15) * 4;
        *(uint2*)&Qs[d * 72 + n4] = *(const uint2*)&qb[(size_t)d * NSP + n0 + n4];
    }

    float o[8][4];
    #pragma unroll
    for (int j = 0; j < 8; j++)
        #pragma unroll
        for (int k = 0; k < 4; k++) o[j][k] = 0.f;
    float osum[4] = {0.f, 0.f, 0.f, 0.f};
    float mr0 = -1e30f, mr1 = -1e30f;
    const float csc = 0.125f * 1.4426950408889634f;
    const uint32_t ONE2 = 0x3C003C00u;

    for (int kt = 0; kt < 16; kt++) {
        int s = kt & 1;
        CP_WAIT0;
        __syncthreads();
        if (kt < 15) issue(kt + 1, s ^ 1);
        uint32_t ka = kbuf[s] + koff;
        uint32_t va = kbuf[s] + voff;

        float sc[8][4];
        #pragma unroll
        for (int j = 0; j < 8; j++)
            #pragma unroll
            for (int k = 0; k < 4; k++) sc[j][k] = 0.f;
        #pragma unroll
        for (int dk = 0; dk < 4; dk++) {
            uint32_t a[4];
            ldsm4t(a[0], a[1], a[2], a[3], qa + dk * 16 * 144);
            #pragma unroll
            for (int jj = 0; jj < 4; jj++) {
                uint32_t bq[4];
                ldsm4t(bq[0], bq[1], bq[2], bq[3], ka + dk * 16 * 144 + jj * 32);
                mmaf16(sc[2 * jj], a, bq[0], bq[1]);
                mmaf16(sc[2 * jj + 1], a, bq[2], bq[3]);
            }
        }

        float tm0 = -1e30f, tm1 = -1e30f;
        #pragma unroll
        for (int j = 0; j < 8; j++) {
            tm0 = fmaxf(tm0, fmaxf(sc[j][0], sc[j][1]));
            tm1 = fmaxf(tm1, fmaxf(sc[j][2], sc[j][3]));
        }
        tm0 = fmaxf(tm0, __shfl_xor_sync(0xffffffffu, tm0, 1));
        tm0 = fmaxf(tm0, __shfl_xor_sync(0xffffffffu, tm0, 2));
        tm1 = fmaxf(tm1, __shfl_xor_sync(0xffffffffu, tm1, 1));
        tm1 = fmaxf(tm1, __shfl_xor_sync(0xffffffffu, tm1, 2));
        float nm0 = fmaxf(mr0, tm0), nm1 = fmaxf(mr1, tm1);
        float cr0f = ex2((mr0 - nm0) * csc), cr1f = ex2((mr1 - nm1) * csc);
        mr0 = nm0; mr1 = nm1;
        float b0 = nm0 * csc, b1 = nm1 * csc;

        uint32_t ph[16];
        #pragma unroll
        for (int q = 0; q < 8; q++) {
            ph[2 * q]     = h2ex2(packh2(fmaf(sc[q][0], csc, -b0), fmaf(sc[q][1], csc, -b0)));
            ph[2 * q + 1] = h2ex2(packh2(fmaf(sc[q][2], csc, -b1), fmaf(sc[q][3], csc, -b1)));
        }

        #pragma unroll
        for (int j = 0; j < 8; j++) {
            o[j][0] *= cr0f; o[j][1] *= cr0f;
            o[j][2] *= cr1f; o[j][3] *= cr1f;
        }
        osum[0] *= cr0f; osum[1] *= cr0f; osum[2] *= cr1f; osum[3] *= cr1f;

        #pragma unroll
        for (int kk = 0; kk < 4; kk++) {
            mmaf16(osum, &ph[4 * kk], ONE2, ONE2);
            #pragma unroll
            for (int dd = 0; dd < 4; dd++) {
                uint32_t bv[4];
                ldsm4(bv[0], bv[1], bv[2], bv[3], va + dd * 16 * 144 + kk * 32);
                mmaf16(o[2 * dd],     &ph[4 * kk], bv[0], bv[1]);
                mmaf16(o[2 * dd + 1], &ph[4 * kk], bv[2], bv[3]);
            }
        }
    }

    float il0 = 1.f / osum[0], il1 = 1.f / osum[2];
    __syncthreads();
    __half* Osm = (__half*)smc;   // [64 d][72 q]
    #pragma unroll
    for (int j = 0; j < 8; j++) {
        int d = 8 * j + 2 * c;
        Osm[(d)     * 72 + prow + r]     = __float2half(o[j][0] * il0);
        Osm[(d + 1) * 72 + prow + r]     = __float2half(o[j][1] * il0);
        Osm[(d)     * 72 + prow + r + 8] = __float2half(o[j][2] * il1);
        Osm[(d + 1) * 72 + prow + r + 8] = __float2half(o[j][3] * il1);
    }
    __syncthreads();
    __half* aob = ao + ((size_t)b * C_ + hh * HD) * NSP;
    #pragma unroll
    for (int i = 0; i < 8; i++) {
        int f = tid + i * 128;
        int d = f >> 4, n4 = (f & 15) * 4;
        *(uint2*)&aob[(size_t)d * NSP + n0 + n4] = *(uint2*)&Osm[d * 72 + n4];
    }
}

// ---------------------------------------------------------------------------
extern "C" void kernel_launch(void* const* d_in, const int* in_sizes, int n_in,
                              void* d_out, int out_size) {
    const float* x      = (const float*)d_in[0];
    const float* gamma  = (const float*)d_in[1];
    const float* beta   = (const float*)d_in[2];
    const float* w_qkv  = (const float*)d_in[3];
    const float* b_qkv  = (const float*)d_in[4];
    const float* w_proj = (const float*)d_in[5];
    const float* b_proj = (const float*)d_in[6];
    float* out = (float*)d_out;

    __half *ph, *pq, *pa, *pwq, *pwp;
    cudaGetSymbolAddress((void**)&ph,  g_h);
    cudaGetSymbolAddress((void**)&pq,  g_qkv);
    cudaGetSymbolAddress((void**)&pa,  g_ao);
    cudaGetSymbolAddress((void**)&pwq, g_wqkv);
    cudaGetSymbolAddress((void**)&pwp, g_wprj);

    cudaFuncSetAttribute(attn_f16, cudaFuncAttributeMaxDynamicSharedMemorySize, ATTN_SMEM);
    cudaFuncSetAttribute(gemm_f16, cudaFuncAttributeMaxDynamicSharedMemorySize, GSMEM);

    prolog_kernel<<<1024, 512>>>(x, gamma, beta, ph, w_qkv, pwq, w_proj, pwp);

    cudaLaunchAttribute attrs[1];
    attrs[0].id = cudaLaunchAttributeProgrammaticStreamSerialization;
    attrs[0].val.programmaticStreamSerializationAllowed = 1;

    {   // QKV GEMM
        cudaLaunchConfig_t cfg = {};
        cfg.gridDim = dim3(8, 12, 16);
        cfg.blockDim = dim3(128, 1, 1);
        cfg.dynamicSmemBytes = GSMEM;
        cfg.stream = 0;
        cfg.attrs = attrs;
        cfg.numAttrs = 1;
        cudaLaunchKernelEx(&cfg, gemm_f16, (const __half*)pwq, (const __half*)ph,
                           b_qkv, (const float*)nullptr, (float*)nullptr, pq);
    }
    {   // attention
        cudaLaunchConfig_t cfg = {};
        cfg.gridDim = dim3(16, NH, B_);
        cfg.blockDim = dim3(128, 1, 1);
        cfg.dynamicSmemBytes = ATTN_SMEM;
        cfg.stream = 0;
        cfg.attrs = attrs;
        cfg.numAttrs = 1;
        cudaLaunchKernelEx(&cfg, attn_f16, (const __half*)pq, pa);
    }
    {   // proj GEMM + residual
        cudaLaunchConfig_t cfg = {};
        cfg.gridDim = dim3(8, 4, 16);
        cfg.blockDim = dim3(128, 1, 1);
        cfg.dynamicSmemBytes = GSMEM;
        cfg.stream = 0;
        cfg.attrs = attrs;
        cfg.numAttrs = 1;
        cudaLaunchKernelEx(&cfg, gemm_f16, (const __half*)pwp, (const __half*)pa,
                           b_proj, x, out, (__half*)nullptr);
    }
}